// round 4
// baseline (speedup 1.0000x reference)
#include <cuda_runtime.h>
#include <math.h>

#define BB 256
#define SS 365
#define FD 32
#define FS 27
#define HH 256
#define G3 768

#define OUT_OFF   0
#define HN_OFF    93440
#define CN_OFF    24014080

#define WSTRIDE 260
#define NCOL 96                    // columns per CTA (3 gates x 32 i)
#define HSM_OFF (NCOL * WSTRIDE)   // h_sm starts after w_sm

typedef unsigned long long u64;

__device__ float g_xproj[(size_t)SS * G3 * BB];   // [s][col][b]
__device__ float g_h[2][BB * HH];

__device__ __forceinline__ u64 ffma2(u64 a, u64 b, u64 c) {
    u64 d;
    asm("fma.rn.f32x2 %0, %1, %2, %3;" : "=l"(d) : "l"(a), "l"(b), "l"(c));
    return d;
}
__device__ __forceinline__ u64 dup2(float x) {
    u64 r;
    asm("mov.b64 %0, {%1, %1};" : "=l"(r) : "f"(x));
    return r;
}
__device__ __forceinline__ float sigm_f(float x) {
    return __fdividef(1.0f, 1.0f + __expf(-x));
}
__device__ __forceinline__ float tanh_f(float x) {
    float t = __expf(2.0f * x);
    return 1.0f - __fdividef(2.0f, t + 1.0f);
}

__global__ void reset_kernel() {
    int idx = blockIdx.x * blockDim.x + threadIdx.x;
    if (idx < BB * HH) g_h[0][idx] = 0.0f;
}

// x_proj precompute with packed f32x2. grid: S blocks, 256 threads (thread = b).
// smem: W_ih pair-interleaved: smf[p*64 + d*2 + half] = W_ih[d][2p+half]
__global__ void __launch_bounds__(256) xproj_kernel(const float* __restrict__ x_d,
                                                    const float* __restrict__ W_ih) {
    extern __shared__ float smf[];  // 384*64 floats = 98304 B
    const int s = blockIdx.x;
    const int tid = threadIdx.x;

    for (int idx = tid; idx < FD * G3; idx += 256) {
        int d = idx / G3, col = idx % G3;
        smf[(col >> 1) * 64 + d * 2 + (col & 1)] = W_ih[idx];
    }
    __syncthreads();

    // x row duplicated into f32x2 registers
    u64 xp[FD];
    {
        const float4* xp4 = reinterpret_cast<const float4*>(x_d + ((size_t)tid * SS + s) * FD);
#pragma unroll
        for (int m = 0; m < 8; m++) {
            float4 v = xp4[m];
            xp[4*m]   = dup2(v.x);
            xp[4*m+1] = dup2(v.y);
            xp[4*m+2] = dup2(v.z);
            xp[4*m+3] = dup2(v.w);
        }
    }

    float* dst = g_xproj + (size_t)s * G3 * BB + tid;
    for (int p = 0; p < G3 / 2; p++) {
        u64 acc = 0ull;
        const ulonglong2* wp = reinterpret_cast<const ulonglong2*>(&smf[p * 64]);
#pragma unroll
        for (int dd = 0; dd < 16; dd++) {
            ulonglong2 q = wp[dd];
            acc = ffma2(xp[2*dd],     q.x, acc);
            acc = ffma2(xp[2*dd + 1], q.y, acc);
        }
        float2 pr = *reinterpret_cast<float2*>(&acc);
        dst[(size_t)(2*p)     * BB] = pr.x;
        dst[(size_t)(2*p + 1) * BB] = pr.y;
    }
}

// Persistent recurrence: grid 128 = 16 clusters x 8 CTAs.
// Cluster = batch tile of 16 rows; CTA rank r covers i-block r*32..r*32+31 (96 cols).
// warp w -> 4 i (w*4..w*4+3); lane: ks=lane>>3 (k quarter), bg=lane&7.
// Thread owns b = bt*16 + bg + 8*(ks&1), i pair = w*4 + 2*(ks>>1) + {0,1}.
__global__ void __launch_bounds__(256, 1) __cluster_dims__(8, 1, 1)
ealstm_kernel(const float* __restrict__ x_s,
              const float* __restrict__ W_hh,
              const float* __restrict__ W_sh,
              const float* __restrict__ bias,
              const float* __restrict__ bias_s,
              float* __restrict__ d_out) {
    extern __shared__ float smem[];
    float* w_sm = smem;             // [96][260]
    float* h_sm = smem + HSM_OFF;   // [16][260]

    const int tid  = threadIdx.x;
    const int warp = tid >> 5;
    const int lane = tid & 31;
    const int ks   = lane >> 3;
    const int bg   = lane & 7;
    const int bt   = blockIdx.x >> 3;   // cluster index = batch tile
    const int r    = blockIdx.x & 7;    // rank in cluster = i-block

    // ---- load W_hh slice: w_sm[c][k], c = gate*32 + il ----
    for (int idx = tid; idx < NCOL * HH; idx += 256) {
        int c = idx % NCOL, k = idx / NCOL;
        int gate = c >> 5, il = c & 31;
        w_sm[c * WSTRIDE + k] = W_hh[k * G3 + gate * HH + r * 32 + il];
    }

    const int b_own   = bt * 16 + bg + 8 * (ks & 1);
    const int i_loc2  = warp * 4 + 2 * (ks >> 1);
    const int i_glob  = r * 32 + i_loc2;

    float bf[2], bo[2], bgc[2], ig[2], creg[2];
#pragma unroll
    for (int il = 0; il < 2; il++) {
        int i = i_glob + il;
        bf[il]  = bias[i];
        bo[il]  = bias[HH + i];
        bgc[il] = bias[2 * HH + i];
        float sum = bias_s[i];
        for (int d = 0; d < FS; d++)
            sum = fmaf(x_s[b_own * FS + d], W_sh[d * HH + i], sum);
        ig[il] = 1.0f / (1.0f + expf(-sum));
        creg[il] = 0.0f;
    }
    __syncthreads();

    const int kofs = ks * 64;
    int hrow[2], wrow[12];
#pragma unroll
    for (int jj = 0; jj < 2; jj++) hrow[jj] = (bg + 8 * jj) * WSTRIDE + kofs;
#pragma unroll
    for (int g = 0; g < 3; g++)
#pragma unroll
        for (int ci = 0; ci < 4; ci++)
            wrow[g * 4 + ci] = (g * 32 + warp * 4 + ci) * WSTRIDE + kofs;

    for (int s = 0; s < SS; s++) {
        // ---- prefetch x_proj terms for this step (independent of barrier) ----
        float xf[2], xo[2], xg[2];
        {
            const size_t xrow = (size_t)s * G3 * BB + b_own;
#pragma unroll
            for (int il = 0; il < 2; il++) {
                int i = i_glob + il;
                xf[il] = __ldcg(&g_xproj[xrow + (size_t)i * BB]);
                xo[il] = __ldcg(&g_xproj[xrow + (size_t)(HH + i) * BB]);
                xg[il] = __ldcg(&g_xproj[xrow + (size_t)(2 * HH + i) * BB]);
            }
        }

        // ---- wait for previous step's arrives (all 8 CTAs of cluster) ----
        if (s > 0) {
            asm volatile("barrier.cluster.wait.aligned;" ::: "memory");
        }

        // ---- load h tile [16 x 256] from L2 double buffer ----
        {
            const float4* hs4 = reinterpret_cast<const float4*>(g_h[s & 1] + (size_t)bt * 16 * HH);
#pragma unroll
            for (int m = 0; m < 4; m++) {
                int f = m * 256 + tid;
                float4 v = __ldcg(hs4 + f);
                int F = f * 4;
                *reinterpret_cast<float4*>(&h_sm[(F >> 8) * WSTRIDE + (F & 255)]) = v;
            }
        }
        __syncthreads();

        // ---- packed f32x2 accumulation over this lane's k quarter ----
        u64 acc[2][12];
#pragma unroll
        for (int jj = 0; jj < 2; jj++)
#pragma unroll
            for (int c = 0; c < 12; c++) acc[jj][c] = 0ull;

#pragma unroll 4
        for (int kk = 0; kk < 16; kk++) {
            const int o = kk * 4;
            ulonglong2 h2[2];
#pragma unroll
            for (int jj = 0; jj < 2; jj++)
                h2[jj] = *reinterpret_cast<const ulonglong2*>(&h_sm[hrow[jj] + o]);
#pragma unroll
            for (int c = 0; c < 12; c++) {
                ulonglong2 w2 = *reinterpret_cast<const ulonglong2*>(&w_sm[wrow[c] + o]);
#pragma unroll
                for (int jj = 0; jj < 2; jj++) {
                    acc[jj][c] = ffma2(h2[jj].x, w2.x, acc[jj][c]);
                    acc[jj][c] = ffma2(h2[jj].y, w2.y, acc[jj][c]);
                }
            }
        }

        // ---- horizontal add + reduce over k quarters ----
        float accs[2][12];
#pragma unroll
        for (int jj = 0; jj < 2; jj++)
#pragma unroll
            for (int c = 0; c < 12; c++) {
                float2 p = *reinterpret_cast<float2*>(&acc[jj][c]);
                float v = p.x + p.y;
                v += __shfl_xor_sync(0xffffffffu, v, 8);
                v += __shfl_xor_sync(0xffffffffu, v, 16);
                accs[jj][c] = v;
            }

        // ---- select this thread's 6 gate values (b via ks&1, i-pair via ks&2) ----
        float g6[6];
#pragma unroll
        for (int g = 0; g < 3; g++)
#pragma unroll
            for (int il = 0; il < 2; il++) {
                float va = (ks & 2) ? accs[0][g*4 + 2 + il] : accs[0][g*4 + il];
                float vb = (ks & 2) ? accs[1][g*4 + 2 + il] : accs[1][g*4 + il];
                g6[g * 2 + il] = (ks & 1) ? vb : va;
            }

        // ---- gate epilogue ----
        float hv[2], cv[2];
#pragma unroll
        for (int il = 0; il < 2; il++) {
            float f = g6[il]     + bf[il]  + xf[il];
            float o = g6[2 + il] + bo[il]  + xo[il];
            float g = g6[4 + il] + bgc[il] + xg[il];
            float cn = sigm_f(f) * creg[il] + ig[il] * tanh_f(g);
            float hn = sigm_f(o) * tanh_f(cn);
            creg[il] = cn;
            hv[il] = hn; cv[il] = cn;
        }

        // ---- publish h' (critical path), arrive, then cold outputs ----
        float2 h2v = make_float2(hv[0], hv[1]);
        float2 c2v = make_float2(cv[0], cv[1]);
        __stcg(reinterpret_cast<float2*>(&g_h[(s + 1) & 1][b_own * HH + i_glob]), h2v);

        asm volatile("barrier.cluster.arrive.aligned;" ::: "memory");

        {
            size_t obase = ((size_t)b_own * SS + s) * HH + i_glob;
            *reinterpret_cast<float2*>(&d_out[HN_OFF + obase]) = h2v;
            *reinterpret_cast<float2*>(&d_out[CN_OFF + obase]) = c2v;
        }
    }
    // drain final arrive
    asm volatile("barrier.cluster.wait.aligned;" ::: "memory");
}

__global__ void __launch_bounds__(256) fc_kernel(const float* __restrict__ W_fc,
                                                 const float* __restrict__ b_fc,
                                                 float* __restrict__ d_out) {
    int gidx = blockIdx.x * 8 + (threadIdx.x >> 5);
    if (gidx >= BB * SS) return;
    int lane = threadIdx.x & 31;

    const float4* h4 = reinterpret_cast<const float4*>(d_out + HN_OFF + (size_t)gidx * HH) + lane * 2;
    const float4* w4 = reinterpret_cast<const float4*>(W_fc) + lane * 2;
    float4 a = h4[0], b = h4[1];
    float4 wa = w4[0], wb = w4[1];
    float sum = a.x * wa.x + a.y * wa.y + a.z * wa.z + a.w * wa.w
              + b.x * wb.x + b.y * wb.y + b.z * wb.z + b.w * wb.w;
#pragma unroll
    for (int off = 16; off > 0; off >>= 1)
        sum += __shfl_xor_sync(0xffffffffu, sum, off);
    if (lane == 0) d_out[OUT_OFF + gidx] = sum + b_fc[0];
}

extern "C" void kernel_launch(void* const* d_in, const int* in_sizes, int n_in,
                              void* d_out, int out_size) {
    const float* x_d    = (const float*)d_in[0];
    const float* x_s    = (const float*)d_in[1];
    const float* W_ih   = (const float*)d_in[2];
    const float* W_hh   = (const float*)d_in[3];
    const float* W_sh   = (const float*)d_in[4];
    const float* bias   = (const float*)d_in[5];
    const float* bias_s = (const float*)d_in[6];
    const float* W_fc   = (const float*)d_in[7];
    const float* b_fc   = (const float*)d_in[8];
    float* out = (float*)d_out;

    const int SMEM_X    = (G3 / 2) * 64 * sizeof(float);                   // 98304
    const int SMEM_MAIN = (NCOL * WSTRIDE + 16 * WSTRIDE) * sizeof(float); // 116480

    cudaFuncSetAttribute(xproj_kernel, cudaFuncAttributeMaxDynamicSharedMemorySize, SMEM_X);
    cudaFuncSetAttribute(ealstm_kernel, cudaFuncAttributeMaxDynamicSharedMemorySize, SMEM_MAIN);

    reset_kernel<<<256, 256>>>();
    xproj_kernel<<<SS, 256, SMEM_X>>>(x_d, W_ih);
    ealstm_kernel<<<128, 256, SMEM_MAIN>>>(x_s, W_hh, W_sh, bias, bias_s, out);
    fc_kernel<<<(BB * SS + 7) / 8, 256>>>(W_fc, b_fc, out);
}

// round 6
// speedup vs baseline: 1.8406x; 1.8406x over previous
#include <cuda_runtime.h>
#include <math.h>

#define BB 256
#define SS 365
#define FD 32
#define FS 27
#define HH 256
#define G3 768

#define OUT_OFF   0
#define HN_OFF    93440
#define CN_OFF    24014080

#define WSTRIDE 260
#define HSM_OFF (48 * WSTRIDE)

typedef unsigned long long u64;

__device__ float g_xproj[(size_t)SS * G3 * BB];   // [s][col][b]
__device__ int   g_flag[8 * 32];                  // group bt at bt*32 (128B apart), 16 used each

__device__ __forceinline__ u64 ffma2(u64 a, u64 b, u64 c) {
    u64 d;
    asm("fma.rn.f32x2 %0, %1, %2, %3;" : "=l"(d) : "l"(a), "l"(b), "l"(c));
    return d;
}
__device__ __forceinline__ u64 dup2(float x) {
    u64 r;
    asm("mov.b64 %0, {%1, %1};" : "=l"(r) : "f"(x));
    return r;
}
__device__ __forceinline__ float sigm_f(float x) {
    return __fdividef(1.0f, 1.0f + __expf(-x));
}
__device__ __forceinline__ float tanh_f(float x) {
    float t = __expf(2.0f * x);
    return 1.0f - __fdividef(2.0f, t + 1.0f);
}

__global__ void reset_kernel() {
    int idx = blockIdx.x * blockDim.x + threadIdx.x;
    if (idx < 8 * 32) g_flag[idx] = 0;
}

// x_proj precompute with packed f32x2. grid: S blocks, 256 threads (thread = b).
__global__ void __launch_bounds__(256) xproj_kernel(const float* __restrict__ x_d,
                                                    const float* __restrict__ W_ih) {
    extern __shared__ float smf[];  // [pair][d*2+half], 384*64 floats
    const int s = blockIdx.x;
    const int tid = threadIdx.x;

    for (int idx = tid; idx < FD * G3; idx += 256) {
        int d = idx / G3, col = idx % G3;
        smf[(col >> 1) * 64 + d * 2 + (col & 1)] = W_ih[idx];
    }
    __syncthreads();

    u64 xp[FD];
    {
        const float4* xp4 = reinterpret_cast<const float4*>(x_d + ((size_t)tid * SS + s) * FD);
#pragma unroll
        for (int m = 0; m < 8; m++) {
            float4 v = xp4[m];
            xp[4*m]   = dup2(v.x);
            xp[4*m+1] = dup2(v.y);
            xp[4*m+2] = dup2(v.z);
            xp[4*m+3] = dup2(v.w);
        }
    }

    float* dst = g_xproj + (size_t)s * G3 * BB + tid;
    for (int p = 0; p < G3 / 2; p++) {
        u64 acc = 0ull;
        const ulonglong2* wp = reinterpret_cast<const ulonglong2*>(&smf[p * 64]);
#pragma unroll
        for (int dd = 0; dd < 16; dd++) {
            ulonglong2 q = wp[dd];
            acc = ffma2(xp[2*dd],     q.x, acc);
            acc = ffma2(xp[2*dd + 1], q.y, acc);
        }
        float2 pr = *reinterpret_cast<float2*>(&acc);
        dst[(size_t)(2*p)     * BB] = pr.x;
        dst[(size_t)(2*p + 1) * BB] = pr.y;
    }
}

// Persistent recurrence: grid 128 = 8 batch tiles (32 b) x 16 CTAs (48 cols).
// warp w -> i pair {ic*16+2w, +1}; lane: ks=lane>>3 (k quarter), bg=lane&7.
__global__ void __launch_bounds__(256, 1) ealstm_kernel(const float* __restrict__ x_s,
                                                        const float* __restrict__ W_hh,
                                                        const float* __restrict__ W_sh,
                                                        const float* __restrict__ bias,
                                                        const float* __restrict__ bias_s,
                                                        float* __restrict__ d_out) {
    extern __shared__ float smem[];
    float* w_sm = smem;             // [48][260]
    float* h_sm = smem + HSM_OFF;   // [32][260]

    const int tid  = threadIdx.x;
    const int warp = tid >> 5;
    const int lane = tid & 31;
    const int ks   = lane >> 3;
    const int bg   = lane & 7;
    const int bt   = blockIdx.x >> 4;
    const int ic   = blockIdx.x & 15;

    for (int idx = tid; idx < 48 * 256; idx += 256) {
        int c = idx % 48, k = idx / 48;
        int gate = c >> 4, il = c & 15;
        w_sm[c * WSTRIDE + k] = W_hh[k * G3 + gate * HH + ic * 16 + il];
    }

    const int b_glob = bt * 32 + bg + 8 * ks;
    const int i0     = ic * 16 + warp * 2;

    float bf[2], bo[2], bgc[2], ig[2], creg[2];
#pragma unroll
    for (int il = 0; il < 2; il++) {
        int i = i0 + il;
        bf[il]  = bias[i];
        bo[il]  = bias[HH + i];
        bgc[il] = bias[2 * HH + i];
        float sum = bias_s[i];
        for (int d = 0; d < FS; d++)
            sum = fmaf(x_s[b_glob * FS + d], W_sh[d * HH + i], sum);
        ig[il] = 1.0f / (1.0f + expf(-sum));
        creg[il] = 0.0f;
    }
    __syncthreads();

    const int kofs = ks * 64;
    int hrow[4], wrow[6];
#pragma unroll
    for (int j = 0; j < 4; j++) hrow[j] = (bg + 8 * j) * WSTRIDE + kofs;
#pragma unroll
    for (int g = 0; g < 3; g++)
#pragma unroll
        for (int il = 0; il < 2; il++)
            wrow[g * 2 + il] = (g * 16 + warp * 2 + il) * WSTRIDE + kofs;

    // h tile: 32 rows x 256 cols = 2048 float4; thread handles f = m*256 + tid, m in [0,8)
    // row = f>>6 = m*4 + (tid>>6), k = (f&63)*4
    const int hl_row = tid >> 6;          // 0..3
    const int hl_k   = (tid & 63) * 4;

    int* my_flag = &g_flag[bt * 32 + ic];

    for (int s = 0; s < SS; s++) {
        // ---- prefetch x_proj additive terms (independent of sync) ----
        float xf[2], xo[2], xg[2];
        {
            const size_t xrow = (size_t)s * G3 * BB + b_glob;
#pragma unroll
            for (int il = 0; il < 2; il++) {
                int i = i0 + il;
                xf[il] = __ldcg(&g_xproj[xrow + (size_t)i * BB]);
                xo[il] = __ldcg(&g_xproj[xrow + (size_t)(HH + i) * BB]);
                xg[il] = __ldcg(&g_xproj[xrow + (size_t)(2 * HH + i) * BB]);
            }
        }

        if (s == 0) {
            // h = 0 : all 32 rows
#pragma unroll
            for (int m = 0; m < 8; m++) {
                int rl = 4 * m + hl_row;
                *reinterpret_cast<float4*>(&h_sm[rl * WSTRIDE + hl_k]) =
                    make_float4(0.f, 0.f, 0.f, 0.f);
            }
            __syncthreads();
        } else {
            // ---- wait: all 16 producer flags of this group >= s ----
            if (warp == 0 && lane < 16) {
                const int* fp = &g_flag[bt * 32 + lane];
                int v;
                do {
                    asm volatile("ld.acquire.gpu.global.b32 %0, [%1];"
                                 : "=r"(v) : "l"(fp) : "memory");
                } while (v < s);
            }
            __syncthreads();

            // ---- load h tile [32 x 256] from d_out h_n region (step s-1) ----
#pragma unroll
            for (int m = 0; m < 8; m++) {
                int rl = 4 * m + hl_row;
                const float* src = d_out + HN_OFF +
                    ((size_t)(bt * 32 + rl) * SS + (s - 1)) * HH + hl_k;
                float4 v = __ldcg(reinterpret_cast<const float4*>(src));
                *reinterpret_cast<float4*>(&h_sm[rl * WSTRIDE + hl_k]) = v;
            }
            __syncthreads();
        }

        // ---- packed f32x2 accumulation over this lane's k quarter ----
        u64 acc[4][6];
#pragma unroll
        for (int j = 0; j < 4; j++)
#pragma unroll
            for (int c = 0; c < 6; c++) acc[j][c] = 0ull;

#pragma unroll 4
        for (int kk = 0; kk < 16; kk++) {
            const int o = kk * 4;
            ulonglong2 h2[4];
#pragma unroll
            for (int j = 0; j < 4; j++)
                h2[j] = *reinterpret_cast<const ulonglong2*>(&h_sm[hrow[j] + o]);
#pragma unroll
            for (int c = 0; c < 6; c++) {
                ulonglong2 w2 = *reinterpret_cast<const ulonglong2*>(&w_sm[wrow[c] + o]);
#pragma unroll
                for (int j = 0; j < 4; j++) {
                    acc[j][c] = ffma2(h2[j].x, w2.x, acc[j][c]);
                    acc[j][c] = ffma2(h2[j].y, w2.y, acc[j][c]);
                }
            }
        }

        // ---- horizontal add + reduce over k quarters ----
        float accs[4][6];
#pragma unroll
        for (int j = 0; j < 4; j++)
#pragma unroll
            for (int c = 0; c < 6; c++) {
                float2 p = *reinterpret_cast<float2*>(&acc[j][c]);
                float v = p.x + p.y;
                v += __shfl_xor_sync(0xffffffffu, v, 8);
                v += __shfl_xor_sync(0xffffffffu, v, 16);
                accs[j][c] = v;
            }

        float g6[6];
#pragma unroll
        for (int c = 0; c < 6; c++) {
            float v0 = (ks & 1) ? accs[1][c] : accs[0][c];
            float v2 = (ks & 1) ? accs[3][c] : accs[2][c];
            g6[c] = (ks & 2) ? v2 : v0;
        }

        // ---- gate epilogue ----
        float hv[2], cv[2];
#pragma unroll
        for (int il = 0; il < 2; il++) {
            float f = g6[il]     + bf[il]  + xf[il];
            float o = g6[2 + il] + bo[il]  + xo[il];
            float g = g6[4 + il] + bgc[il] + xg[il];
            float cn = sigm_f(f) * creg[il] + ig[il] * tanh_f(g);
            float hn = sigm_f(o) * tanh_f(cn);
            creg[il] = cn;
            hv[il] = hn; cv[il] = cn;
        }

        // ---- publish h' to d_out (L2), release flag, then cold c ----
        size_t obase = ((size_t)b_glob * SS + s) * HH + i0;
        __stcg(reinterpret_cast<float2*>(&d_out[HN_OFF + obase]), make_float2(hv[0], hv[1]));

        __syncthreads();   // all warps' h' stores issued before the flag release
        if (tid == 0) {
            asm volatile("st.release.gpu.global.b32 [%0], %1;"
                         :: "l"(my_flag), "r"(s + 1) : "memory");
        }

        *reinterpret_cast<float2*>(&d_out[CN_OFF + obase]) = make_float2(cv[0], cv[1]);
    }
}

__global__ void __launch_bounds__(256) fc_kernel(const float* __restrict__ W_fc,
                                                 const float* __restrict__ b_fc,
                                                 float* __restrict__ d_out) {
    int gidx = blockIdx.x * 8 + (threadIdx.x >> 5);
    if (gidx >= BB * SS) return;
    int lane = threadIdx.x & 31;

    const float4* h4 = reinterpret_cast<const float4*>(d_out + HN_OFF + (size_t)gidx * HH) + lane * 2;
    const float4* w4 = reinterpret_cast<const float4*>(W_fc) + lane * 2;
    float4 a = h4[0], b = h4[1];
    float4 wa = w4[0], wb = w4[1];
    float sum = a.x * wa.x + a.y * wa.y + a.z * wa.z + a.w * wa.w
              + b.x * wb.x + b.y * wb.y + b.z * wb.z + b.w * wb.w;
#pragma unroll
    for (int off = 16; off > 0; off >>= 1)
        sum += __shfl_xor_sync(0xffffffffu, sum, off);
    if (lane == 0) d_out[OUT_OFF + gidx] = sum + b_fc[0];
}

extern "C" void kernel_launch(void* const* d_in, const int* in_sizes, int n_in,
                              void* d_out, int out_size) {
    const float* x_d    = (const float*)d_in[0];
    const float* x_s    = (const float*)d_in[1];
    const float* W_ih   = (const float*)d_in[2];
    const float* W_hh   = (const float*)d_in[3];
    const float* W_sh   = (const float*)d_in[4];
    const float* bias   = (const float*)d_in[5];
    const float* bias_s = (const float*)d_in[6];
    const float* W_fc   = (const float*)d_in[7];
    const float* b_fc   = (const float*)d_in[8];
    float* out = (float*)d_out;

    const int SMEM_X    = (G3 / 2) * 64 * sizeof(float);                 // 98304
    const int SMEM_MAIN = (48 * WSTRIDE + 32 * WSTRIDE) * sizeof(float); // 83200

    cudaFuncSetAttribute(xproj_kernel, cudaFuncAttributeMaxDynamicSharedMemorySize, SMEM_X);
    cudaFuncSetAttribute(ealstm_kernel, cudaFuncAttributeMaxDynamicSharedMemorySize, SMEM_MAIN);

    reset_kernel<<<1, 256>>>();
    xproj_kernel<<<SS, 256, SMEM_X>>>(x_d, W_ih);
    ealstm_kernel<<<128, 256, SMEM_MAIN>>>(x_s, W_hh, W_sh, bias, bias_s, out);
    fc_kernel<<<(BB * SS + 7) / 8, 256>>>(W_fc, b_fc, out);
}